// round 5
// baseline (speedup 1.0000x reference)
#include <cuda_runtime.h>
#include <cuda_bf16.h>
#include <stdint.h>
#include <math.h>

#define BQ 16
#define HD 512
#define LL 2048
#define NL 4
#define NN 32
#define NTOT (BQ * LL)  // 32768 total columns

// ---------------- scratch (static __device__, no allocs) ----------------
__device__ float g_H[(size_t)BQ * HD * LL];          // V buffer ping
__device__ float g_G[(size_t)BQ * HD * LL];          // V buffer pong
__device__ float g_mu[2][(size_t)NTOT];              // LN stats ping-pong
__device__ float g_rs[2][(size_t)NTOT];
__device__ __nv_bfloat16 g_Bth[(size_t)NTOT * HD];   // activations (n,k) hi
__device__ __nv_bfloat16 g_Btl[(size_t)NTOT * HD];   // activations (n,k) lo
#define W_ENC_OFF 0
#define W_OUT_OFF (HD * HD)
#define W_DEC_OFF (HD * HD + NL * 2 * HD * HD)
#define W_ELEMS (2 * HD * HD + NL * 2 * HD * HD)
__device__ __nv_bfloat16 g_Wh[W_ELEMS];
__device__ __nv_bfloat16 g_Wl[W_ELEMS];
__device__ float g_wre[NL * HD * NN];
__device__ float g_wim[NL * HD * NN];
__device__ float g_cre[NL * HD * NN];
__device__ float g_cim[NL * HD * NN];

// ---------------- helpers ----------------
__device__ __forceinline__ uint32_t smem_u32(const void* p)
{
    uint32_t a;
    asm("{ .reg .u64 t; cvta.to.shared.u64 t, %1; cvt.u32.u64 %0, t; }"
        : "=r"(a) : "l"(p));
    return a;
}

__device__ __forceinline__ void cp_async16(uint32_t dst, const void* src)
{
    asm volatile("cp.async.cg.shared.global [%0], [%1], 16;" :: "r"(dst), "l"(src));
}
#define CP_COMMIT() asm volatile("cp.async.commit_group;" ::: "memory")
#define CP_WAIT(n)  asm volatile("cp.async.wait_group %0;" :: "n"(n) : "memory")

__device__ __forceinline__ void ldmx4(uint32_t* r, uint32_t addr)
{
    asm volatile("ldmatrix.sync.aligned.m8n8.x4.shared.b16 {%0,%1,%2,%3}, [%4];"
                 : "=r"(r[0]), "=r"(r[1]), "=r"(r[2]), "=r"(r[3]) : "r"(addr));
}

__device__ __forceinline__ void mma16816(float* c, const uint32_t* a,
                                         const uint32_t* b)
{
    asm volatile(
        "mma.sync.aligned.m16n8k16.row.col.f32.bf16.bf16.f32 "
        "{%0,%1,%2,%3}, {%4,%5,%6,%7}, {%8,%9}, {%0,%1,%2,%3};"
        : "+f"(c[0]), "+f"(c[1]), "+f"(c[2]), "+f"(c[3])
        : "r"(a[0]), "r"(a[1]), "r"(a[2]), "r"(a[3]), "r"(b[0]), "r"(b[1]));
}

// ---------------- parameter precompute ----------------
__global__ __launch_bounds__(256)
void precompute_kernel(const float* __restrict__ log_dt,
                       const float* __restrict__ log_A_real,
                       const float* __restrict__ A_imag,
                       const float* __restrict__ C_re,
                       const float* __restrict__ C_im)
{
    int idx = blockIdx.x * 256 + threadIdx.x;
    if (idx >= NL * HD * NN) return;
    int h = (idx >> 5) & (HD - 1);
    int l = idx >> 14;
    float dt = expf(log_dt[l * HD + h]);
    float a = -expf(log_A_real[idx]);
    float b = A_imag[idx];
    float xr = dt * a, xi = dt * b;
    float er = expf(xr);
    float c = cosf(xi), s = sinf(xi);
    g_wre[idx] = er * c;
    g_wim[idx] = er * s;
    float sh = sinf(0.5f * xi);
    float Ere = expm1f(xr) * c - 2.f * sh * sh;
    float Eim = er * s;
    float den = a * a + b * b;
    float Fre = (Ere * a + Eim * b) / den;
    float Fim = (Eim * a - Ere * b) / den;
    float cr = C_re[idx], ci = C_im[idx];
    g_cre[idx] = cr * Fre - ci * Fim;
    g_cim[idx] = cr * Fim + ci * Fre;
}

// ---------------- weight split fp32 -> bf16 hi/lo ----------------
__global__ __launch_bounds__(256)
void split_w_kernel(const float* __restrict__ src, __nv_bfloat16* __restrict__ hi,
                    __nv_bfloat16* __restrict__ lo, int n)
{
    int i = blockIdx.x * 256 + threadIdx.x;
    if (i >= n) return;
    float v = src[i];
    __nv_bfloat16 h = __float2bfloat16(v);
    hi[i] = h;
    lo[i] = __float2bfloat16(v - __bfloat162float(h));
}

// ---------------- transpose + split (+opt quant / +opt inline LN) ----------
template <bool QUANT, bool NORM>
__global__ __launch_bounds__(256)
void transpose_split_kernel(const float* __restrict__ src,
                            __nv_bfloat16* __restrict__ dhi,
                            __nv_bfloat16* __restrict__ dlo,
                            const float* __restrict__ mu,
                            const float* __restrict__ rs,
                            const float* __restrict__ lng,
                            const float* __restrict__ lnb)
{
    __shared__ float tile[32][33];
    const int b = blockIdx.z;
    const int c0 = blockIdx.y * 32;
    const int t0 = blockIdx.x * 32;
    const int tx = threadIdx.x & 31, ty = threadIdx.x >> 5;
#pragma unroll
    for (int i = 0; i < 32; i += 8) {
        const int c = c0 + ty + i;
        float v = src[((size_t)b * HD + c) * LL + t0 + tx];
        if (QUANT) v = rintf(v * 64.f) * 0.015625f;
        if (NORM) {
            float a = rs[(size_t)b * LL + t0 + tx] * lng[c];
            v = fmaf(v - mu[(size_t)b * LL + t0 + tx], a, lnb[c]);
        }
        tile[ty + i][tx] = v;
    }
    __syncthreads();
#pragma unroll
    for (int i = 0; i < 32; i += 8) {
        int t = t0 + ty + i;
        int c = c0 + tx;
        float v = tile[tx][ty + i];
        __nv_bfloat16 h = __float2bfloat16(v);
        size_t o = ((size_t)b * LL + t) * HD + c;
        dhi[o] = h;
        dlo[o] = __float2bfloat16(v - __bfloat162float(h));
    }
}

// ---------------- HMMA GEMM (3x bf16 split, fp32 acc) ----------------
// EPI 0: relu -> out (128 M rows per CTA)
// EPI 2: fused GLU + residual (+opt LN of prev): A rows interleave z1/z2
//        16-row blocks; writes V = (z1+b1)*sigmoid(z2+b2) + hn, 64 rows/CTA.
#define KC 64
#define TILE_BYTES 16384            // 128 * 64 * 2B
#define STAGE_BYTES (4 * TILE_BYTES)
#define GEMM_SMEM (2 * STAGE_BYTES) // 131072

template <int EPI, int NORM>
__global__ __launch_bounds__(256, 1)
void gemm_mma(const __nv_bfloat16* __restrict__ Wh, const __nv_bfloat16* __restrict__ Wl,
              const __nv_bfloat16* __restrict__ Xh, const __nv_bfloat16* __restrict__ Xl,
              float* __restrict__ out, const float* __restrict__ bias, int M,
              const float* __restrict__ Vprev, const float* __restrict__ mu,
              const float* __restrict__ rs, const float* __restrict__ lng,
              const float* __restrict__ lnb)
{
    extern __shared__ char smem[];
    const uint32_t sb = smem_u32(smem);
    const int tid = threadIdx.x;
    const int wid = tid >> 5, lane = tid & 31;
    const int wm = wid >> 1, wn = wid & 1;
    const int n0 = blockIdx.x * 128;
    const int m0 = blockIdx.y * ((EPI == 2) ? 64 : 128);
    const int lr = lane & 7, lg = lane >> 3;

    float acc[2][8][4];
#pragma unroll
    for (int i = 0; i < 2; ++i)
#pragma unroll
        for (int j = 0; j < 8; ++j)
#pragma unroll
            for (int q = 0; q < 4; ++q) acc[i][j][q] = 0.f;

    auto load_chunk = [&](int kc, int st) {
        const uint32_t base = sb + st * STAGE_BYTES;
        const size_t gk = (size_t)kc * KC;
#pragma unroll
        for (int i = 0; i < 4; ++i) {
            int lin = i * 256 + tid;
            int row = lin >> 3, seg = lin & 7;
            uint32_t soff = row * 128 + (((seg ^ (row & 7))) << 4);
            int wrow;
            if (EPI == 2)
                wrow = ((row >> 4) & 1) * HD + m0 + (row >> 5) * 16 + (row & 15);
            else
                wrow = m0 + row;
            const size_t wgo = (size_t)wrow * HD + gk + seg * 8;
            const size_t xgo = (size_t)(n0 + row) * HD + gk + seg * 8;
            cp_async16(base + soff, Wh + wgo);
            cp_async16(base + TILE_BYTES + soff, Wl + wgo);
            cp_async16(base + 2 * TILE_BYTES + soff, Xh + xgo);
            cp_async16(base + 3 * TILE_BYTES + soff, Xl + xgo);
        }
        CP_COMMIT();
    };

    load_chunk(0, 0);

    const int NCH = HD / KC;  // 8
    for (int c = 0; c < NCH; ++c) {
        if (c + 1 < NCH) {
            load_chunk(c + 1, (c + 1) & 1);
            CP_WAIT(1);
        } else {
            CP_WAIT(0);
        }
        __syncthreads();

        const uint32_t stg = sb + (c & 1) * STAGE_BYTES;
#pragma unroll
        for (int ks = 0; ks < 4; ++ks) {
            uint32_t a[2][2][4];
            uint32_t b[2][4][4];
#pragma unroll
            for (int mi = 0; mi < 2; ++mi) {
                int arow = wm * 32 + mi * 16 + lr + (lg & 1) * 8;
                int aseg = ks * 2 + (lg >> 1);
                uint32_t off = arow * 128 + ((aseg ^ (arow & 7)) << 4);
                ldmx4(a[0][mi], stg + off);
                ldmx4(a[1][mi], stg + TILE_BYTES + off);
            }
#pragma unroll
            for (int g = 0; g < 4; ++g) {
                int brow = wn * 64 + g * 16 + lr + (lg >> 1) * 8;
                int bseg = ks * 2 + (lg & 1);
                uint32_t off = brow * 128 + ((bseg ^ (brow & 7)) << 4);
                ldmx4(b[0][g], stg + 2 * TILE_BYTES + off);
                ldmx4(b[1][g], stg + 3 * TILE_BYTES + off);
            }
#pragma unroll
            for (int mi = 0; mi < 2; ++mi)
#pragma unroll
                for (int j = 0; j < 8; ++j) {
                    const int g = j >> 1, p = (j & 1) * 2;
                    uint32_t bh[2] = {b[0][g][p], b[0][g][p + 1]};
                    uint32_t bl[2] = {b[1][g][p], b[1][g][p + 1]};
                    mma16816(acc[mi][j], a[0][mi], bh);
                    mma16816(acc[mi][j], a[0][mi], bl);
                    mma16816(acc[mi][j], a[1][mi], bh);
                }
        }
        __syncthreads();
    }

    // ---------------- epilogue ----------------
    if (EPI == 2) {
        const int m = m0 + wm * 16 + (lane >> 2);
        const float b10 = bias[m],      b18 = bias[m + 8];
        const float b20 = bias[HD + m], b28 = bias[HD + m + 8];
        float g1 = 0.f, g2 = 0.f, o1 = 0.f, o2 = 0.f;
        if (NORM) {
            g1 = lng[m];  g2 = lng[m + 8];
            o1 = lnb[m];  o2 = lnb[m + 8];
        }
#pragma unroll
        for (int j = 0; j < 8; ++j) {
            const int n = n0 + wn * 64 + j * 8 + (lane & 3) * 2;
            const int bb = n >> 11;
            const int t = n & (LL - 1);
            float z10 = acc[0][j][0] + b10, z11 = acc[0][j][1] + b10;
            float z12 = acc[0][j][2] + b18, z13 = acc[0][j][3] + b18;
            float z20 = acc[1][j][0] + b20, z21 = acc[1][j][1] + b20;
            float z22 = acc[1][j][2] + b28, z23 = acc[1][j][3] + b28;
            float gl0 = z10 / (1.f + expf(-z20));
            float gl1 = z11 / (1.f + expf(-z21));
            float gl2 = z12 / (1.f + expf(-z22));
            float gl3 = z13 / (1.f + expf(-z23));
            const float2 p0 = *reinterpret_cast<const float2*>(
                Vprev + ((size_t)bb * HD + m) * LL + t);
            const float2 p1 = *reinterpret_cast<const float2*>(
                Vprev + ((size_t)bb * HD + m + 8) * LL + t);
            float h0x, h0y, h1x, h1y;
            if (NORM) {
                const float2 muv = *reinterpret_cast<const float2*>(mu + (size_t)bb * LL + t);
                const float2 rsv = *reinterpret_cast<const float2*>(rs + (size_t)bb * LL + t);
                h0x = fmaf(p0.x - muv.x, rsv.x * g1, o1);
                h0y = fmaf(p0.y - muv.y, rsv.y * g1, o1);
                h1x = fmaf(p1.x - muv.x, rsv.x * g2, o2);
                h1y = fmaf(p1.y - muv.y, rsv.y * g2, o2);
            } else {
                h0x = p0.x; h0y = p0.y; h1x = p1.x; h1y = p1.y;
            }
            float2 v0, v1;
            v0.x = gl0 + h0x; v0.y = gl1 + h0y;
            v1.x = gl2 + h1x; v1.y = gl3 + h1y;
            *reinterpret_cast<float2*>(out + ((size_t)bb * HD + m) * LL + t) = v0;
            *reinterpret_cast<float2*>(out + ((size_t)bb * HD + m + 8) * LL + t) = v1;
        }
    } else {
#pragma unroll
        for (int mi = 0; mi < 2; ++mi) {
            const int mrow0 = m0 + wm * 32 + mi * 16 + (lane >> 2);
#pragma unroll
            for (int j = 0; j < 8; ++j) {
                const int n = n0 + wn * 64 + j * 8 + (lane & 3) * 2;
                const int bb = n >> 11;
                const int t = n & (LL - 1);
                float2 v0, v1;
                v0.x = fmaxf(acc[mi][j][0], 0.f);
                v0.y = fmaxf(acc[mi][j][1], 0.f);
                v1.x = fmaxf(acc[mi][j][2], 0.f);
                v1.y = fmaxf(acc[mi][j][3], 0.f);
                *reinterpret_cast<float2*>(out + ((size_t)bb * M + mrow0) * LL + t) = v0;
                *reinterpret_cast<float2*>(out + ((size_t)bb * M + mrow0 + 8) * LL + t) = v1;
            }
        }
    }
}

// ---------------- per-(b,t) LN stats over channels ----------------
__global__ __launch_bounds__(256)
void stats_kernel(const float* __restrict__ V, float* __restrict__ mu_out,
                  float* __restrict__ rs_out)
{
    __shared__ float ssum[4][64];
    __shared__ float ssq[4][64];
    const int b = blockIdx.y;
    const int tl = threadIdx.x & 63;
    const int slab = threadIdx.x >> 6;
    const size_t t = (size_t)blockIdx.x * 64 + tl;
    const float* Vb = V + (size_t)b * HD * LL;

    float s = 0.f, s2 = 0.f;
    for (int c = slab * 128; c < slab * 128 + 128; ++c) {
        float v = Vb[(size_t)c * LL + t];
        s += v;
        s2 = fmaf(v, v, s2);
    }
    ssum[slab][tl] = s;
    ssq[slab][tl] = s2;
    __syncthreads();
    if (slab == 0) {
        float st = ssum[0][tl] + ssum[1][tl] + ssum[2][tl] + ssum[3][tl];
        float st2 = ssq[0][tl] + ssq[1][tl] + ssq[2][tl] + ssq[3][tl];
        float m = st * (1.f / HD);
        float var = st2 * (1.f / HD) - m * m;
        mu_out[(size_t)b * LL + t] = m;
        rs_out[(size_t)b * LL + t] = rsqrtf(var + 1e-5f);
    }
}

// ---------------- SSM scan (+opt inline LN of input) -> bf16 hi/lo T ------
template <bool NORM>
__global__ __launch_bounds__(256)
void ssm_scan_fused(const float* __restrict__ vbuf,
                    const float* __restrict__ mu, const float* __restrict__ rs,
                    const float* __restrict__ lng, const float* __restrict__ lnb,
                    __nv_bfloat16* __restrict__ dhi,
                    __nv_bfloat16* __restrict__ dlo,
                    const float* __restrict__ wre, const float* __restrict__ wim,
                    const float* __restrict__ ccre, const float* __restrict__ ccim,
                    const float* __restrict__ Dv)
{
    __shared__ float tile[32][33];
    const int tid = threadIdx.x;
    const int q = tid & 7;
    const int g = tid >> 3;                 // 0..31
    const int grp0 = blockIdx.x * 32;
    const int grp = grp0 + g;
    const int b = grp >> 9;
    const int hh = grp & (HD - 1);
    const int h0 = grp0 & (HD - 1);
    const float* vrow = vbuf + (size_t)grp * LL;
    const float* murow = NORM ? (mu + (size_t)b * LL) : nullptr;
    const float* rsrow = NORM ? (rs + (size_t)b * LL) : nullptr;
    const float lgh = NORM ? lng[hh] : 0.f;
    const float lbh = NORM ? lnb[hh] : 0.f;

    const int pbase = hh * NN + q * 4;
    float4 w_r = *reinterpret_cast<const float4*>(&wre[pbase]);
    float4 w_i = *reinterpret_cast<const float4*>(&wim[pbase]);
    float4 c_r = *reinterpret_cast<const float4*>(&ccre[pbase]);
    float4 c_i = *reinterpret_cast<const float4*>(&ccim[pbase]);
    float wr[4] = {w_r.x, w_r.y, w_r.z, w_r.w};
    float wi[4] = {w_i.x, w_i.y, w_i.z, w_i.w};
    float cr[4] = {c_r.x, c_r.y, c_r.z, c_r.w};
    float ci[4] = {c_i.x, c_i.y, c_i.z, c_i.w};
    const float Dh = Dv[hh];

    float sr[4] = {0.f, 0.f, 0.f, 0.f};
    float si[4] = {0.f, 0.f, 0.f, 0.f};

    const int tt = tid >> 3, seg = tid & 7;

    for (int t0 = 0; t0 < LL; t0 += 32) {
#pragma unroll
        for (int sub = 0; sub < 4; ++sub) {
            const int tb = t0 + sub * 8;
            float umine = 0.f, ykeep = 0.f;
#pragma unroll
            for (int j = 0; j < 8; ++j) {
                float u = vrow[tb + j];
                if (NORM) {
                    float a = rsrow[tb + j] * lgh;
                    u = fmaf(u - murow[tb + j], a, lbh);
                }
#pragma unroll
                for (int k = 0; k < 4; ++k) {
                    float nr = fmaf(wr[k], sr[k], u);
                    nr = fmaf(-wi[k], si[k], nr);
                    float ni = wr[k] * si[k];
                    ni = fmaf(wi[k], sr[k], ni);
                    sr[k] = nr;
                    si[k] = ni;
                }
                float acc = 0.f;
#pragma unroll
                for (int k = 0; k < 4; ++k) {
                    acc = fmaf(cr[k], sr[k], acc);
                    acc = fmaf(-ci[k], si[k], acc);
                }
                acc += __shfl_xor_sync(0xffffffffu, acc, 1);
                acc += __shfl_xor_sync(0xffffffffu, acc, 2);
                acc += __shfl_xor_sync(0xffffffffu, acc, 4);
                if (j == q) { umine = u; ykeep = acc; }
            }
            float yv = fmaf(Dh, umine, 2.f * ykeep);
            float gv = 0.5f * yv * (1.f + erff(yv * 0.70710678118654752f));
            tile[sub * 8 + q][g] = gv;
        }
        __syncthreads();
        {
            const int t = t0 + tt;
            float v0 = tile[tt][seg * 4 + 0];
            float v1 = tile[tt][seg * 4 + 1];
            float v2 = tile[tt][seg * 4 + 2];
            float v3 = tile[tt][seg * 4 + 3];
            __nv_bfloat16 hi4[4], lo4[4];
            hi4[0] = __float2bfloat16(v0);
            hi4[1] = __float2bfloat16(v1);
            hi4[2] = __float2bfloat16(v2);
            hi4[3] = __float2bfloat16(v3);
            lo4[0] = __float2bfloat16(v0 - __bfloat162float(hi4[0]));
            lo4[1] = __float2bfloat16(v1 - __bfloat162float(hi4[1]));
            lo4[2] = __float2bfloat16(v2 - __bfloat162float(hi4[2]));
            lo4[3] = __float2bfloat16(v3 - __bfloat162float(hi4[3]));
            const size_t o = ((size_t)b * LL + t) * HD + h0 + seg * 4;
            *reinterpret_cast<uint2*>(dhi + o) = *reinterpret_cast<uint2*>(hi4);
            *reinterpret_cast<uint2*>(dlo + o) = *reinterpret_cast<uint2*>(lo4);
        }
        __syncthreads();
    }
}

// ---------------- launch ----------------
extern "C" void kernel_launch(void* const* d_in, const int* in_sizes, int n_in,
                              void* d_out, int out_size)
{
    const float* x = (const float*)d_in[0];
    const float* W_enc = (const float*)d_in[1];
    const float* W_dec = (const float*)d_in[2];
    const float* log_dt = (const float*)d_in[3];
    const float* log_A_real = (const float*)d_in[4];
    const float* A_imag = (const float*)d_in[5];
    const float* C_re = (const float*)d_in[6];
    const float* C_im = (const float*)d_in[7];
    const float* Dv = (const float*)d_in[8];
    const float* W_out = (const float*)d_in[9];
    const float* b_out = (const float*)d_in[10];
    const float* ln_g = (const float*)d_in[11];
    const float* ln_b = (const float*)d_in[12];
    float* out = (float*)d_out;

    float *pH, *pG, *pwre, *pwim, *pcre, *pcim, *pmu0, *pmu1, *prs0, *prs1;
    __nv_bfloat16 *pBth, *pBtl, *pWh, *pWl;
    cudaGetSymbolAddress((void**)&pH, g_H);
    cudaGetSymbolAddress((void**)&pG, g_G);
    cudaGetSymbolAddress((void**)&pwre, g_wre);
    cudaGetSymbolAddress((void**)&pwim, g_wim);
    cudaGetSymbolAddress((void**)&pcre, g_cre);
    cudaGetSymbolAddress((void**)&pcim, g_cim);
    cudaGetSymbolAddress((void**)&pBth, g_Bth);
    cudaGetSymbolAddress((void**)&pBtl, g_Btl);
    cudaGetSymbolAddress((void**)&pWh, g_Wh);
    cudaGetSymbolAddress((void**)&pWl, g_Wl);
    cudaGetSymbolAddress((void**)&pmu0, g_mu);  pmu1 = pmu0 + NTOT;
    cudaGetSymbolAddress((void**)&prs0, g_rs);  prs1 = prs0 + NTOT;

    cudaFuncSetAttribute(gemm_mma<0, 0>, cudaFuncAttributeMaxDynamicSharedMemorySize, GEMM_SMEM);
    cudaFuncSetAttribute(gemm_mma<2, 0>, cudaFuncAttributeMaxDynamicSharedMemorySize, GEMM_SMEM);
    cudaFuncSetAttribute(gemm_mma<2, 1>, cudaFuncAttributeMaxDynamicSharedMemorySize, GEMM_SMEM);

    precompute_kernel<<<(NL * HD * NN + 255) / 256, 256>>>(log_dt, log_A_real,
                                                           A_imag, C_re, C_im);
    split_w_kernel<<<(HD * HD + 255) / 256, 256>>>(W_enc, pWh + W_ENC_OFF,
                                                   pWl + W_ENC_OFF, HD * HD);
    split_w_kernel<<<(NL * 2 * HD * HD + 255) / 256, 256>>>(
        W_out, pWh + W_OUT_OFF, pWl + W_OUT_OFF, NL * 2 * HD * HD);
    split_w_kernel<<<(HD * HD + 255) / 256, 256>>>(W_dec, pWh + W_DEC_OFF,
                                                   pWl + W_DEC_OFF, HD * HD);

    const dim3 tgrid(LL / 32, HD / 32, BQ);

    // encoder: h = relu(W_enc @ quant(x)) -> g_H (raw, no LN)
    transpose_split_kernel<true, false><<<tgrid, 256>>>(x, pBth, pBtl,
                                                        nullptr, nullptr, nullptr, nullptr);
    gemm_mma<0, 0><<<dim3(NTOT / 128, HD / 128), 256, GEMM_SMEM>>>(
        pWh + W_ENC_OFF, pWl + W_ENC_OFF, pBth, pBtl, pH, nullptr, HD,
        nullptr, nullptr, nullptr, nullptr, nullptr);

    float* vbuf[2] = {pH, pG};
    float* mus[2] = {pmu0, pmu1};
    float* rss[2] = {prs0, prs1};

    for (int l = 0; l < NL; ++l) {
        const int po = l * HD * NN;
        float* Vin = vbuf[l & 1];          // V(l-1) (or raw enc h for l=0)
        float* Vout = vbuf[(l + 1) & 1];
        const int sIn = (l - 1) & 1;       // stats of V(l-1)
        const int sOut = l & 1;
        const float* lnpg = ln_g + (l - 1) * HD;
        const float* lnpb = ln_b + (l - 1) * HD;

        if (l == 0) {
            ssm_scan_fused<false><<<(BQ * HD) / 32, 256>>>(
                Vin, nullptr, nullptr, nullptr, nullptr, pBth, pBtl,
                pwre + po, pwim + po, pcre + po, pcim + po, Dv + l * HD);
            gemm_mma<2, 0><<<dim3(NTOT / 128, HD / 64), 256, GEMM_SMEM>>>(
                pWh + W_OUT_OFF + (size_t)l * 2 * HD * HD,
                pWl + W_OUT_OFF + (size_t)l * 2 * HD * HD,
                pBth, pBtl, Vout, b_out + l * 2 * HD, HD,
                Vin, nullptr, nullptr, nullptr, nullptr);
        } else {
            ssm_scan_fused<true><<<(BQ * HD) / 32, 256>>>(
                Vin, mus[sIn], rss[sIn], lnpg, lnpb, pBth, pBtl,
                pwre + po, pwim + po, pcre + po, pcim + po, Dv + l * HD);
            gemm_mma<2, 1><<<dim3(NTOT / 128, HD / 64), 256, GEMM_SMEM>>>(
                pWh + W_OUT_OFF + (size_t)l * 2 * HD * HD,
                pWl + W_OUT_OFF + (size_t)l * 2 * HD * HD,
                pBth, pBtl, Vout, b_out + l * 2 * HD, HD,
                Vin, mus[sIn], rss[sIn], lnpg, lnpb);
        }
        stats_kernel<<<dim3(LL / 64, BQ), 256>>>(Vout, mus[sOut], rss[sOut]);
    }

    // decoder: out = relu(W_dec @ LN(V3))
    float* Vlast = vbuf[NL & 1];           // V(3)
    const int sLast = (NL - 1) & 1;
    transpose_split_kernel<false, true><<<tgrid, 256>>>(
        Vlast, pBth, pBtl, mus[sLast], rss[sLast],
        ln_g + (NL - 1) * HD, ln_b + (NL - 1) * HD);
    gemm_mma<0, 0><<<dim3(NTOT / 128, HD / 128), 256, GEMM_SMEM>>>(
        pWh + W_DEC_OFF, pWl + W_DEC_OFF, pBth, pBtl, out, nullptr, HD,
        nullptr, nullptr, nullptr, nullptr, nullptr);
}

// round 6
// speedup vs baseline: 1.1079x; 1.1079x over previous
#include <cuda_runtime.h>
#include <cuda_bf16.h>
#include <stdint.h>
#include <math.h>

#define BQ 16
#define HD 512
#define LL 2048
#define NL 4
#define NN 32
#define NTOT (BQ * LL)  // 32768 total columns

// ---------------- scratch (static __device__, no allocs) ----------------
__device__ float g_H[(size_t)BQ * HD * LL];          // normalized stream Hn
__device__ float g_V[(size_t)BQ * HD * LL];          // pre-norm V scratch
__device__ __nv_bfloat16 g_Bth[(size_t)NTOT * HD];   // activations (n,k) hi
__device__ __nv_bfloat16 g_Btl[(size_t)NTOT * HD];   // activations (n,k) lo
#define W_ENC_OFF 0
#define W_OUT_OFF (HD * HD)
#define W_DEC_OFF (HD * HD + NL * 2 * HD * HD)
#define W_ELEMS (2 * HD * HD + NL * 2 * HD * HD)
__device__ __nv_bfloat16 g_Wh[W_ELEMS];
__device__ __nv_bfloat16 g_Wl[W_ELEMS];
__device__ float g_wre[NL * HD * NN];
__device__ float g_wim[NL * HD * NN];
__device__ float g_cre[NL * HD * NN];
__device__ float g_cim[NL * HD * NN];

// ---------------- helpers ----------------
__device__ __forceinline__ uint32_t smem_u32(const void* p)
{
    uint32_t a;
    asm("{ .reg .u64 t; cvta.to.shared.u64 t, %1; cvt.u32.u64 %0, t; }"
        : "=r"(a) : "l"(p));
    return a;
}

__device__ __forceinline__ void cp_async16(uint32_t dst, const void* src)
{
    asm volatile("cp.async.cg.shared.global [%0], [%1], 16;" :: "r"(dst), "l"(src));
}
#define CP_COMMIT() asm volatile("cp.async.commit_group;" ::: "memory")
#define CP_WAIT(n)  asm volatile("cp.async.wait_group %0;" :: "n"(n) : "memory")

__device__ __forceinline__ void ldmx4(uint32_t* r, uint32_t addr)
{
    asm volatile("ldmatrix.sync.aligned.m8n8.x4.shared.b16 {%0,%1,%2,%3}, [%4];"
                 : "=r"(r[0]), "=r"(r[1]), "=r"(r[2]), "=r"(r[3]) : "r"(addr));
}

__device__ __forceinline__ void mma16816(float* c, const uint32_t* a,
                                         const uint32_t* b)
{
    asm volatile(
        "mma.sync.aligned.m16n8k16.row.col.f32.bf16.bf16.f32 "
        "{%0,%1,%2,%3}, {%4,%5,%6,%7}, {%8,%9}, {%0,%1,%2,%3};"
        : "+f"(c[0]), "+f"(c[1]), "+f"(c[2]), "+f"(c[3])
        : "r"(a[0]), "r"(a[1]), "r"(a[2]), "r"(a[3]), "r"(b[0]), "r"(b[1]));
}

// ---------------- parameter precompute ----------------
__global__ __launch_bounds__(256)
void precompute_kernel(const float* __restrict__ log_dt,
                       const float* __restrict__ log_A_real,
                       const float* __restrict__ A_imag,
                       const float* __restrict__ C_re,
                       const float* __restrict__ C_im)
{
    int idx = blockIdx.x * 256 + threadIdx.x;
    if (idx >= NL * HD * NN) return;
    int h = (idx >> 5) & (HD - 1);
    int l = idx >> 14;
    float dt = expf(log_dt[l * HD + h]);
    float a = -expf(log_A_real[idx]);
    float b = A_imag[idx];
    float xr = dt * a, xi = dt * b;
    float er = expf(xr);
    float c = cosf(xi), s = sinf(xi);
    g_wre[idx] = er * c;
    g_wim[idx] = er * s;
    float sh = sinf(0.5f * xi);
    float Ere = expm1f(xr) * c - 2.f * sh * sh;
    float Eim = er * s;
    float den = a * a + b * b;
    float Fre = (Ere * a + Eim * b) / den;
    float Fim = (Eim * a - Ere * b) / den;
    float cr = C_re[idx], ci = C_im[idx];
    g_cre[idx] = cr * Fre - ci * Fim;
    g_cim[idx] = cr * Fim + ci * Fre;
}

// ---------------- weight split fp32 -> bf16 hi/lo ----------------
__global__ __launch_bounds__(256)
void split_w_kernel(const float* __restrict__ src, __nv_bfloat16* __restrict__ hi,
                    __nv_bfloat16* __restrict__ lo, int n)
{
    int i = blockIdx.x * 256 + threadIdx.x;
    if (i >= n) return;
    float v = src[i];
    __nv_bfloat16 h = __float2bfloat16(v);
    hi[i] = h;
    lo[i] = __float2bfloat16(v - __bfloat162float(h));
}

// ---------------- transpose + split (+opt quant) ----------
template <bool QUANT>
__global__ __launch_bounds__(256)
void transpose_split_kernel(const float* __restrict__ src,
                            __nv_bfloat16* __restrict__ dhi,
                            __nv_bfloat16* __restrict__ dlo)
{
    __shared__ float tile[32][33];
    const int b = blockIdx.z;
    const int c0 = blockIdx.y * 32;
    const int t0 = blockIdx.x * 32;
    const int tx = threadIdx.x & 31, ty = threadIdx.x >> 5;
#pragma unroll
    for (int i = 0; i < 32; i += 8) {
        float v = src[((size_t)b * HD + c0 + ty + i) * LL + t0 + tx];
        if (QUANT) v = rintf(v * 64.f) * 0.015625f;
        tile[ty + i][tx] = v;
    }
    __syncthreads();
#pragma unroll
    for (int i = 0; i < 32; i += 8) {
        int t = t0 + ty + i;
        int c = c0 + tx;
        float v = tile[tx][ty + i];
        __nv_bfloat16 h = __float2bfloat16(v);
        size_t o = ((size_t)b * LL + t) * HD + c;
        dhi[o] = h;
        dlo[o] = __float2bfloat16(v - __bfloat162float(h));
    }
}

// ---------------- HMMA GEMM (3x bf16 split, fp32 acc) ----------------
// EPI 0: relu -> out (128 M rows per CTA)
// EPI 2: fused GLU + residual: A rows interleave z1/z2 16-row blocks;
//        writes V = (z1+b1)*sigmoid(z2+b2) + Hn_prev, 64 out rows per CTA.
#define KC 64
#define TILE_BYTES 16384            // 128 * 64 * 2B
#define STAGE_BYTES (4 * TILE_BYTES)
#define GEMM_SMEM (2 * STAGE_BYTES) // 131072

template <int EPI>
__global__ __launch_bounds__(256, 1)
void gemm_mma(const __nv_bfloat16* __restrict__ Wh, const __nv_bfloat16* __restrict__ Wl,
              const __nv_bfloat16* __restrict__ Xh, const __nv_bfloat16* __restrict__ Xl,
              float* __restrict__ out, const float* __restrict__ bias, int M,
              const float* __restrict__ Hprev)
{
    extern __shared__ char smem[];
    const uint32_t sb = smem_u32(smem);
    const int tid = threadIdx.x;
    const int wid = tid >> 5, lane = tid & 31;
    const int wm = wid >> 1, wn = wid & 1;
    const int n0 = blockIdx.x * 128;
    const int m0 = blockIdx.y * ((EPI == 2) ? 64 : 128);
    const int lr = lane & 7, lg = lane >> 3;

    float acc[2][8][4];
#pragma unroll
    for (int i = 0; i < 2; ++i)
#pragma unroll
        for (int j = 0; j < 8; ++j)
#pragma unroll
            for (int q = 0; q < 4; ++q) acc[i][j][q] = 0.f;

    auto load_chunk = [&](int kc, int st) {
        const uint32_t base = sb + st * STAGE_BYTES;
        const size_t gk = (size_t)kc * KC;
#pragma unroll
        for (int i = 0; i < 4; ++i) {
            int lin = i * 256 + tid;
            int row = lin >> 3, seg = lin & 7;
            uint32_t soff = row * 128 + (((seg ^ (row & 7))) << 4);
            int wrow;
            if (EPI == 2)
                wrow = ((row >> 4) & 1) * HD + m0 + (row >> 5) * 16 + (row & 15);
            else
                wrow = m0 + row;
            const size_t wgo = (size_t)wrow * HD + gk + seg * 8;
            const size_t xgo = (size_t)(n0 + row) * HD + gk + seg * 8;
            cp_async16(base + soff, Wh + wgo);
            cp_async16(base + TILE_BYTES + soff, Wl + wgo);
            cp_async16(base + 2 * TILE_BYTES + soff, Xh + xgo);
            cp_async16(base + 3 * TILE_BYTES + soff, Xl + xgo);
        }
        CP_COMMIT();
    };

    load_chunk(0, 0);

    const int NCH = HD / KC;  // 8
    for (int c = 0; c < NCH; ++c) {
        if (c + 1 < NCH) {
            load_chunk(c + 1, (c + 1) & 1);
            CP_WAIT(1);
        } else {
            CP_WAIT(0);
        }
        __syncthreads();

        const uint32_t stg = sb + (c & 1) * STAGE_BYTES;
#pragma unroll
        for (int ks = 0; ks < 4; ++ks) {
            uint32_t a[2][2][4];
            uint32_t b[2][4][4];
#pragma unroll
            for (int mi = 0; mi < 2; ++mi) {
                int arow = wm * 32 + mi * 16 + lr + (lg & 1) * 8;
                int aseg = ks * 2 + (lg >> 1);
                uint32_t off = arow * 128 + ((aseg ^ (arow & 7)) << 4);
                ldmx4(a[0][mi], stg + off);
                ldmx4(a[1][mi], stg + TILE_BYTES + off);
            }
#pragma unroll
            for (int g = 0; g < 4; ++g) {
                int brow = wn * 64 + g * 16 + lr + (lg >> 1) * 8;
                int bseg = ks * 2 + (lg & 1);
                uint32_t off = brow * 128 + ((bseg ^ (brow & 7)) << 4);
                ldmx4(b[0][g], stg + 2 * TILE_BYTES + off);
                ldmx4(b[1][g], stg + 3 * TILE_BYTES + off);
            }
#pragma unroll
            for (int mi = 0; mi < 2; ++mi)
#pragma unroll
                for (int j = 0; j < 8; ++j) {
                    const int g = j >> 1, p = (j & 1) * 2;
                    uint32_t bh[2] = {b[0][g][p], b[0][g][p + 1]};
                    uint32_t bl[2] = {b[1][g][p], b[1][g][p + 1]};
                    mma16816(acc[mi][j], a[0][mi], bh);
                    mma16816(acc[mi][j], a[0][mi], bl);
                    mma16816(acc[mi][j], a[1][mi], bh);
                }
        }
        __syncthreads();
    }

    // ---------------- epilogue ----------------
    if (EPI == 2) {
        const int m = m0 + wm * 16 + (lane >> 2);
        const float b10 = bias[m],      b18 = bias[m + 8];
        const float b20 = bias[HD + m], b28 = bias[HD + m + 8];
#pragma unroll
        for (int j = 0; j < 8; ++j) {
            const int n = n0 + wn * 64 + j * 8 + (lane & 3) * 2;
            const int bb = n >> 11;
            const int t = n & (LL - 1);
            float z10 = acc[0][j][0] + b10, z11 = acc[0][j][1] + b10;
            float z12 = acc[0][j][2] + b18, z13 = acc[0][j][3] + b18;
            float z20 = acc[1][j][0] + b20, z21 = acc[1][j][1] + b20;
            float z22 = acc[1][j][2] + b28, z23 = acc[1][j][3] + b28;
            const float2 p0 = *reinterpret_cast<const float2*>(
                Hprev + ((size_t)bb * HD + m) * LL + t);
            const float2 p1 = *reinterpret_cast<const float2*>(
                Hprev + ((size_t)bb * HD + m + 8) * LL + t);
            float2 v0, v1;
            v0.x = z10 / (1.f + expf(-z20)) + p0.x;
            v0.y = z11 / (1.f + expf(-z21)) + p0.y;
            v1.x = z12 / (1.f + expf(-z22)) + p1.x;
            v1.y = z13 / (1.f + expf(-z23)) + p1.y;
            *reinterpret_cast<float2*>(out + ((size_t)bb * HD + m) * LL + t) = v0;
            *reinterpret_cast<float2*>(out + ((size_t)bb * HD + m + 8) * LL + t) = v1;
        }
    } else {
#pragma unroll
        for (int mi = 0; mi < 2; ++mi) {
            const int mrow0 = m0 + wm * 32 + mi * 16 + (lane >> 2);
#pragma unroll
            for (int j = 0; j < 8; ++j) {
                const int n = n0 + wn * 64 + j * 8 + (lane & 3) * 2;
                const int bb = n >> 11;
                const int t = n & (LL - 1);
                float2 v0, v1;
                v0.x = fmaxf(acc[mi][j][0], 0.f);
                v0.y = fmaxf(acc[mi][j][1], 0.f);
                v1.x = fmaxf(acc[mi][j][2], 0.f);
                v1.y = fmaxf(acc[mi][j][3], 0.f);
                *reinterpret_cast<float2*>(out + ((size_t)bb * M + mrow0) * LL + t) = v0;
                *reinterpret_cast<float2*>(out + ((size_t)bb * M + mrow0 + 8) * LL + t) = v1;
            }
        }
    }
}

// ---------------- single-pass LayerNorm: Hn = LN(V) ----------------
// CTA: 32 t-columns x all 512 channels held in registers (64/thread).
__global__ __launch_bounds__(256)
void ln_kernel(const float* __restrict__ V, float* __restrict__ Hn,
               const float* __restrict__ gamma, const float* __restrict__ beta)
{
    __shared__ float ssum[8][32];
    __shared__ float ssq[8][32];
    const int b = blockIdx.y;
    const int tx = threadIdx.x & 31;
    const int ty = threadIdx.x >> 5;          // 0..7
    const size_t t = (size_t)blockIdx.x * 32 + tx;
    const float* Vb = V + (size_t)b * HD * LL + t;
    float* Hb = Hn + (size_t)b * HD * LL + t;

    float vals[64];
    float s = 0.f, s2 = 0.f;
#pragma unroll
    for (int k = 0; k < 64; ++k) {
        const int c = k * 8 + ty;
        float v = Vb[(size_t)c * LL];
        vals[k] = v;
        s += v;
        s2 = fmaf(v, v, s2);
    }
    ssum[ty][tx] = s;
    ssq[ty][tx] = s2;
    __syncthreads();
    float st = 0.f, st2 = 0.f;
#pragma unroll
    for (int i = 0; i < 8; ++i) {
        st += ssum[i][tx];
        st2 += ssq[i][tx];
    }
    const float mu = st * (1.f / HD);
    const float var = st2 * (1.f / HD) - mu * mu;
    const float rstd = rsqrtf(var + 1e-5f);
#pragma unroll
    for (int k = 0; k < 64; ++k) {
        const int c = k * 8 + ty;
        Hb[(size_t)c * LL] = (vals[k] - mu) * rstd * gamma[c] + beta[c];
    }
}

// ---------------- SSM scan (R4 path + vector loads) -> bf16 hi/lo T ------
__global__ __launch_bounds__(256)
void ssm_scan_fused(const float* __restrict__ hbuf,
                    __nv_bfloat16* __restrict__ dhi,
                    __nv_bfloat16* __restrict__ dlo,
                    const float* __restrict__ wre, const float* __restrict__ wim,
                    const float* __restrict__ ccre, const float* __restrict__ ccim,
                    const float* __restrict__ Dv)
{
    __shared__ float tile[32][33];
    const int tid = threadIdx.x;
    const int q = tid & 7;
    const int g = tid >> 3;                 // 0..31
    const int grp0 = blockIdx.x * 32;
    const int grp = grp0 + g;
    const int b = grp >> 9;
    const int hh = grp & (HD - 1);
    const int h0 = grp0 & (HD - 1);
    const float* hrow = hbuf + (size_t)grp * LL;

    const int pbase = hh * NN + q * 4;
    float4 w_r = *reinterpret_cast<const float4*>(&wre[pbase]);
    float4 w_i = *reinterpret_cast<const float4*>(&wim[pbase]);
    float4 c_r = *reinterpret_cast<const float4*>(&ccre[pbase]);
    float4 c_i = *reinterpret_cast<const float4*>(&ccim[pbase]);
    float wr[4] = {w_r.x, w_r.y, w_r.z, w_r.w};
    float wi[4] = {w_i.x, w_i.y, w_i.z, w_i.w};
    float cr[4] = {c_r.x, c_r.y, c_r.z, c_r.w};
    float ci[4] = {c_i.x, c_i.y, c_i.z, c_i.w};
    const float Dh = Dv[hh];

    float sr[4] = {0.f, 0.f, 0.f, 0.f};
    float si[4] = {0.f, 0.f, 0.f, 0.f};

    const int tt = tid >> 3, seg = tid & 7;

    for (int t0 = 0; t0 < LL; t0 += 32) {
#pragma unroll
        for (int sub = 0; sub < 4; ++sub) {
            const int tb = t0 + sub * 8;
            const float4 ua = *reinterpret_cast<const float4*>(hrow + tb);
            const float4 ub = *reinterpret_cast<const float4*>(hrow + tb + 4);
            const float uu[8] = {ua.x, ua.y, ua.z, ua.w, ub.x, ub.y, ub.z, ub.w};
            float umine = 0.f, ykeep = 0.f;
#pragma unroll
            for (int j = 0; j < 8; ++j) {
                const float u = uu[j];
#pragma unroll
                for (int k = 0; k < 4; ++k) {
                    float nr = fmaf(wr[k], sr[k], u);
                    nr = fmaf(-wi[k], si[k], nr);
                    float ni = wr[k] * si[k];
                    ni = fmaf(wi[k], sr[k], ni);
                    sr[k] = nr;
                    si[k] = ni;
                }
                float acc = 0.f;
#pragma unroll
                for (int k = 0; k < 4; ++k) {
                    acc = fmaf(cr[k], sr[k], acc);
                    acc = fmaf(-ci[k], si[k], acc);
                }
                acc += __shfl_xor_sync(0xffffffffu, acc, 1);
                acc += __shfl_xor_sync(0xffffffffu, acc, 2);
                acc += __shfl_xor_sync(0xffffffffu, acc, 4);
                if (j == q) { umine = u; ykeep = acc; }
            }
            float yv = fmaf(Dh, umine, 2.f * ykeep);
            float gv = 0.5f * yv * (1.f + erff(yv * 0.70710678118654752f));
            tile[sub * 8 + q][g] = gv;
        }
        __syncthreads();
        {
            const int t = t0 + tt;
            float v0 = tile[tt][seg * 4 + 0];
            float v1 = tile[tt][seg * 4 + 1];
            float v2 = tile[tt][seg * 4 + 2];
            float v3 = tile[tt][seg * 4 + 3];
            __nv_bfloat16 hi4[4], lo4[4];
            hi4[0] = __float2bfloat16(v0);
            hi4[1] = __float2bfloat16(v1);
            hi4[2] = __float2bfloat16(v2);
            hi4[3] = __float2bfloat16(v3);
            lo4[0] = __float2bfloat16(v0 - __bfloat162float(hi4[0]));
            lo4[1] = __float2bfloat16(v1 - __bfloat162float(hi4[1]));
            lo4[2] = __float2bfloat16(v2 - __bfloat162float(hi4[2]));
            lo4[3] = __float2bfloat16(v3 - __bfloat162float(hi4[3]));
            const size_t o = ((size_t)b * LL + t) * HD + h0 + seg * 4;
            *reinterpret_cast<uint2*>(dhi + o) = *reinterpret_cast<uint2*>(hi4);
            *reinterpret_cast<uint2*>(dlo + o) = *reinterpret_cast<uint2*>(lo4);
        }
        __syncthreads();
    }
}

// ---------------- launch ----------------
extern "C" void kernel_launch(void* const* d_in, const int* in_sizes, int n_in,
                              void* d_out, int out_size)
{
    const float* x = (const float*)d_in[0];
    const float* W_enc = (const float*)d_in[1];
    const float* W_dec = (const float*)d_in[2];
    const float* log_dt = (const float*)d_in[3];
    const float* log_A_real = (const float*)d_in[4];
    const float* A_imag = (const float*)d_in[5];
    const float* C_re = (const float*)d_in[6];
    const float* C_im = (const float*)d_in[7];
    const float* Dv = (const float*)d_in[8];
    const float* W_out = (const float*)d_in[9];
    const float* b_out = (const float*)d_in[10];
    const float* ln_g = (const float*)d_in[11];
    const float* ln_b = (const float*)d_in[12];
    float* out = (float*)d_out;

    float *pH, *pV, *pwre, *pwim, *pcre, *pcim;
    __nv_bfloat16 *pBth, *pBtl, *pWh, *pWl;
    cudaGetSymbolAddress((void**)&pH, g_H);
    cudaGetSymbolAddress((void**)&pV, g_V);
    cudaGetSymbolAddress((void**)&pwre, g_wre);
    cudaGetSymbolAddress((void**)&pwim, g_wim);
    cudaGetSymbolAddress((void**)&pcre, g_cre);
    cudaGetSymbolAddress((void**)&pcim, g_cim);
    cudaGetSymbolAddress((void**)&pBth, g_Bth);
    cudaGetSymbolAddress((void**)&pBtl, g_Btl);
    cudaGetSymbolAddress((void**)&pWh, g_Wh);
    cudaGetSymbolAddress((void**)&pWl, g_Wl);

    cudaFuncSetAttribute(gemm_mma<0>, cudaFuncAttributeMaxDynamicSharedMemorySize, GEMM_SMEM);
    cudaFuncSetAttribute(gemm_mma<2>, cudaFuncAttributeMaxDynamicSharedMemorySize, GEMM_SMEM);

    precompute_kernel<<<(NL * HD * NN + 255) / 256, 256>>>(log_dt, log_A_real,
                                                           A_imag, C_re, C_im);
    split_w_kernel<<<(HD * HD + 255) / 256, 256>>>(W_enc, pWh + W_ENC_OFF,
                                                   pWl + W_ENC_OFF, HD * HD);
    split_w_kernel<<<(NL * 2 * HD * HD + 255) / 256, 256>>>(
        W_out, pWh + W_OUT_OFF, pWl + W_OUT_OFF, NL * 2 * HD * HD);
    split_w_kernel<<<(HD * HD + 255) / 256, 256>>>(W_dec, pWh + W_DEC_OFF,
                                                   pWl + W_DEC_OFF, HD * HD);

    const dim3 tgrid(LL / 32, HD / 32, BQ);

    // encoder: H = relu(W_enc @ quant(x))
    transpose_split_kernel<true><<<tgrid, 256>>>(x, pBth, pBtl);
    gemm_mma<0><<<dim3(NTOT / 128, HD / 128), 256, GEMM_SMEM>>>(
        pWh + W_ENC_OFF, pWl + W_ENC_OFF, pBth, pBtl, pH, nullptr, HD, nullptr);

    for (int l = 0; l < NL; ++l) {
        const int po = l * HD * NN;
        // scan(H) + gelu -> transposed bf16 hi/lo
        ssm_scan_fused<<<(BQ * HD) / 32, 256>>>(
            pH, pBth, pBtl, pwre + po, pwim + po, pcre + po, pcim + po,
            Dv + l * HD);
        // fused GLU + residual: V = glu(z) + H
        gemm_mma<2><<<dim3(NTOT / 128, HD / 64), 256, GEMM_SMEM>>>(
            pWh + W_OUT_OFF + (size_t)l * 2 * HD * HD,
            pWl + W_OUT_OFF + (size_t)l * 2 * HD * HD,
            pBth, pBtl, pV, b_out + l * 2 * HD, HD, pH);
        // H = LN(V) single pass
        ln_kernel<<<dim3(LL / 32, BQ), 256>>>(pV, pH, ln_g + l * HD,
                                              ln_b + l * HD);
    }

    // decoder: out = relu(W_dec @ H)
    transpose_split_kernel<false><<<tgrid, 256>>>(pH, pBth, pBtl);
    gemm_mma<0><<<dim3(NTOT / 128, HD / 128), 256, GEMM_SMEM>>>(
        pWh + W_DEC_OFF, pWl + W_DEC_OFF, pBth, pBtl, out, nullptr, HD, nullptr);
}